// round 8
// baseline (speedup 1.0000x reference)
#include <cuda_runtime.h>
#include <cuda_bf16.h>
#include <cstdint>

#define B_DIM 16
#define T_DIM 1024
#define V_DIM 128
#define N_ROWS (B_DIM * T_DIM)                  // 16384
#define WARPS_PER_BLOCK 8
#define THREADS_PER_BLOCK (WARPS_PER_BLOCK * 32)   // 256
#define ROWS_PER_WARP 2
#define ROWS_PER_BLOCK (WARPS_PER_BLOCK * ROWS_PER_WARP)   // 16
#define N_BLOCKS (N_ROWS / ROWS_PER_BLOCK)      // 1024
#define POS_SLOTS 24                             // 16 real + 8 pad, 96B (16B aligned)

// Scratch (no device allocation allowed)
__device__ float g_partials[N_BLOCKS];
__device__ int   g_ticket = 0;

__global__ __launch_bounds__(THREADS_PER_BLOCK)
void fused_loss_kernel(const float* __restrict__ logits,
                       const float* __restrict__ targets,
                       float* __restrict__ out)
{
    __shared__ float s_pos[WARPS_PER_BLOCK][ROWS_PER_WARP][POS_SLOTS];
    __shared__ float s_warp[WARPS_PER_BLOCK];
    __shared__ bool  s_is_last;

    const int lane  = threadIdx.x & 31;
    const int wid   = threadIdx.x >> 5;
    const int row0  = (blockIdx.x * WARPS_PER_BLOCK + wid) * ROWS_PER_WARP;
    const unsigned lanemask_lt = (1u << lane) - 1u;

    // ---- Front-batched loads: 2 rows x (logits,targets), float4 per lane ----
    float4 xv0 = reinterpret_cast<const float4*>(logits  + (size_t)row0 * V_DIM)[lane];
    float4 tv0 = reinterpret_cast<const float4*>(targets + (size_t)row0 * V_DIM)[lane];
    float4 xv1 = reinterpret_cast<const float4*>(logits  + (size_t)(row0 + 1) * V_DIM)[lane];
    float4 tv1 = reinterpret_cast<const float4*>(targets + (size_t)(row0 + 1) * V_DIM)[lane];

    float base  = 0.0f;   // sum of max(x,0) - x*t
    float hinge = 0.0f;
    float prod  = 1.0f;   // product of (1 + e^-|x|): 8 factors <= 256, fp32-safe

#pragma unroll
    for (int r = 0; r < ROWS_PER_WARP; r++) {
        float xs[4], ts[4];
        if (r == 0) { xs[0]=xv0.x; xs[1]=xv0.y; xs[2]=xv0.z; xs[3]=xv0.w;
                      ts[0]=tv0.x; ts[1]=tv0.y; ts[2]=tv0.z; ts[3]=tv0.w; }
        else        { xs[0]=xv1.x; xs[1]=xv1.y; xs[2]=xv1.z; xs[3]=xv1.w;
                      ts[0]=tv1.x; ts[1]=tv1.y; ts[2]=tv1.z; ts[3]=tv1.w; }

        // ---- BCE pieces ----
#pragma unroll
        for (int i = 0; i < 4; i++) {
            base += fmaxf(xs[i], 0.0f);
            base  = fmaf(-xs[i], ts[i], base);
            prod *= (1.0f + __expf(-fabsf(xs[i])));
        }

        // ---- Compact positives into smem slots (predicated, no loops) ----
        int cnt = 0;
#pragma unroll
        for (int i = 0; i < 4; i++) {
            bool pi = ts[i] > 0.5f;
            unsigned m = __ballot_sync(0xffffffffu, pi);
            int rank = cnt + __popc(m & lanemask_lt);
            if (pi && rank < 16) s_pos[wid][r][rank] = xs[i];
            cnt += __popc(m);
        }
        int padbase = cnt < 16 ? cnt : 16;
        if (lane < 8) s_pos[wid][r][padbase + lane] = 1.0e30f;
        __syncwarp();

        // ---- c[i]: negatives contribute 1+x, positives self-exclude ----
        float c[4];
#pragma unroll
        for (int i = 0; i < 4; i++)
            c[i] = (ts[i] > 0.5f) ? -1.0e30f : (1.0f + xs[i]);

        // ---- Branchless hinge vs 8 (padded) slots: 2x LDS.128 + 64 ALU/FMA ----
        float4 A  = *reinterpret_cast<const float4*>(&s_pos[wid][r][0]);
        float4 Bq = *reinterpret_cast<const float4*>(&s_pos[wid][r][4]);
        float pk[8] = {A.x, A.y, A.z, A.w, Bq.x, Bq.y, Bq.z, Bq.w};
#pragma unroll
        for (int k = 0; k < 8; k++) {
#pragma unroll
            for (int i = 0; i < 4; i++)
                hinge += fmaxf(c[i] - pk[k], 0.0f);
        }

        // ---- Rare: rows with 9..16 positives (warp-uniform branch, ~2%) ----
        if (cnt > 8) {
            float4 Cq = *reinterpret_cast<const float4*>(&s_pos[wid][r][8]);
            float4 Dq = *reinterpret_cast<const float4*>(&s_pos[wid][r][12]);
            float qk[8] = {Cq.x, Cq.y, Cq.z, Cq.w, Dq.x, Dq.y, Dq.z, Dq.w};
#pragma unroll
            for (int k = 0; k < 8; k++) {
#pragma unroll
                for (int i = 0; i < 4; i++)
                    hinge += fmaxf(c[i] - qk[k], 0.0f);
            }
        }
        // ---- Ultra-rare: >16 positives — shuffle fallback for the overflow ----
        if (cnt > 16) {
            int seen = 0;
#pragma unroll
            for (int i = 0; i < 4; i++) {
                unsigned m = __ballot_sync(0xffffffffu, ts[i] > 0.5f);
                while (m) {
                    int src = __ffs(m) - 1;
                    m &= m - 1;
                    if (seen >= 16) {
                        float pv = __shfl_sync(0xffffffffu, xs[i], src);
                        hinge += fmaxf(c[0] - pv, 0.0f);
                        hinge += fmaxf(c[1] - pv, 0.0f);
                        hinge += fmaxf(c[2] - pv, 0.0f);
                        hinge += fmaxf(c[3] - pv, 0.0f);
                    }
                    seen++;
                }
            }
        }
    }

    // One MUFU log per thread
    float bce = base + __logf(prod);
    float v = 0.7f * bce + 0.3f * hinge;

    // ---- Warp reduce ----
#pragma unroll
    for (int o = 16; o > 0; o >>= 1)
        v += __shfl_xor_sync(0xffffffffu, v, o);
    if (lane == 0) s_warp[wid] = v;
    __syncthreads();

    // ---- Block reduce (warp 0) + publish + ticket ----
    if (wid == 0) {
        float s = (lane < WARPS_PER_BLOCK) ? s_warp[lane] : 0.0f;
#pragma unroll
        for (int o = 16; o > 0; o >>= 1)
            s += __shfl_xor_sync(0xffffffffu, s, o);
        if (lane == 0) {
            g_partials[blockIdx.x] = s;
            __threadfence();
            int t = atomicAdd(&g_ticket, 1);
            s_is_last = (t == N_BLOCKS - 1);
        }
    }
    __syncthreads();

    // ---- Last block: deterministic reduction of 1024 partials ----
    if (s_is_last) {
        __threadfence();
        float s = 0.0f;
#pragma unroll
        for (int i = 0; i < N_BLOCKS / THREADS_PER_BLOCK; i++)   // 4 each
            s += g_partials[threadIdx.x + i * THREADS_PER_BLOCK];
#pragma unroll
        for (int o = 16; o > 0; o >>= 1)
            s += __shfl_xor_sync(0xffffffffu, s, o);
        if (lane == 0) s_warp[wid] = s;
        __syncthreads();
        if (wid == 0) {
            float r2 = (lane < WARPS_PER_BLOCK) ? s_warp[lane] : 0.0f;
#pragma unroll
            for (int o = 16; o > 0; o >>= 1)
                r2 += __shfl_xor_sync(0xffffffffu, r2, o);
            if (lane == 0) {
                out[0] = r2 * (1.0f / ((float)V_DIM * (float)N_ROWS));
                g_ticket = 0;   // reset for graph replay
            }
        }
    }
}

extern "C" void kernel_launch(void* const* d_in, const int* in_sizes, int n_in,
                              void* d_out, int out_size)
{
    const float* logits  = (const float*)d_in[0];
    const float* targets = (const float*)d_in[1];
    float* out = (float*)d_out;

    fused_loss_kernel<<<N_BLOCKS, THREADS_PER_BLOCK>>>(logits, targets, out);
}

// round 9
// speedup vs baseline: 1.0450x; 1.0450x over previous
#include <cuda_runtime.h>
#include <cuda_bf16.h>
#include <cstdint>

#define B_DIM 16
#define T_DIM 1024
#define V_DIM 128
#define N_ROWS (B_DIM * T_DIM)                  // 16384
#define WARPS_PER_BLOCK 8
#define THREADS_PER_BLOCK (WARPS_PER_BLOCK * 32)   // 256
#define ROWS_PER_WARP 2
#define ROWS_PER_BLOCK (WARPS_PER_BLOCK * ROWS_PER_WARP)   // 16
#define N_BLOCKS (N_ROWS / ROWS_PER_BLOCK)      // 1024

// Scratch (no device allocation allowed)
__device__ float g_partials[N_BLOCKS];
__device__ int   g_ticket = 0;

__global__ __launch_bounds__(THREADS_PER_BLOCK)
void fused_loss_kernel(const float* __restrict__ logits,
                       const float* __restrict__ targets,
                       float* __restrict__ out)
{
    __shared__ float s_warp[WARPS_PER_BLOCK];
    __shared__ bool  s_is_last;

    const int lane  = threadIdx.x & 31;
    const int wid   = threadIdx.x >> 5;
    const int row0  = (blockIdx.x * WARPS_PER_BLOCK + wid) * ROWS_PER_WARP;

    // ---- Front-batched streaming loads: 2 rows x (logits,targets) ----
    float4 xv0 = __ldcs(reinterpret_cast<const float4*>(logits  + (size_t)row0 * V_DIM) + lane);
    float4 tv0 = __ldcs(reinterpret_cast<const float4*>(targets + (size_t)row0 * V_DIM) + lane);
    float4 xv1 = __ldcs(reinterpret_cast<const float4*>(logits  + (size_t)(row0 + 1) * V_DIM) + lane);
    float4 tv1 = __ldcs(reinterpret_cast<const float4*>(targets + (size_t)(row0 + 1) * V_DIM) + lane);

    float base = 0.0f;    // sum of max(x,0) - x*t
    float h0 = 0.0f, h1 = 0.0f;   // two hinge accumulators for ILP
    float prod = 1.0f;    // product of (1 + e^-|x|): 8 factors <= 256, fp32-safe

#pragma unroll
    for (int r = 0; r < ROWS_PER_WARP; r++) {
        float xs[4], ts[4];
        if (r == 0) { xs[0]=xv0.x; xs[1]=xv0.y; xs[2]=xv0.z; xs[3]=xv0.w;
                      ts[0]=tv0.x; ts[1]=tv0.y; ts[2]=tv0.z; ts[3]=tv0.w; }
        else        { xs[0]=xv1.x; xs[1]=xv1.y; xs[2]=xv1.z; xs[3]=xv1.w;
                      ts[0]=tv1.x; ts[1]=tv1.y; ts[2]=tv1.z; ts[3]=tv1.w; }

        // ---- Hoist all 4 ballots (VOTE latency overlapped) ----
        unsigned m[4];
#pragma unroll
        for (int i = 0; i < 4; i++)
            m[i] = __ballot_sync(0xffffffffu, ts[i] > 0.5f);

        // ---- BCE pieces ----
#pragma unroll
        for (int i = 0; i < 4; i++) {
            base += fmaxf(xs[i], 0.0f);
            base  = fmaf(-xs[i], ts[i], base);
            prod *= (1.0f + __expf(-fabsf(xs[i])));
        }

        // ---- c[i]: arithmetic self-exclusion (no selects):
        //      negatives: 1+x ; positives: 1+x-1e30 ~ -1e30 ----
        float c[4];
#pragma unroll
        for (int i = 0; i < 4; i++)
            c[i] = fmaf(ts[i], -1.0e30f, 1.0f + xs[i]);

        // ---- Hinge: 2-way peeled shuffle-broadcast of positives ----
#pragma unroll
        for (int i = 0; i < 4; i++) {
            unsigned mm = m[i];
            while (mm) {                                    // warp-uniform
                int s1 = __ffs(mm) - 1; mm &= mm - 1;
                float pv1 = __shfl_sync(0xffffffffu, xs[i], s1);
                if (mm) {
                    int s2 = __ffs(mm) - 1; mm &= mm - 1;
                    float pv2 = __shfl_sync(0xffffffffu, xs[i], s2);
                    // consume pv2 first: pv1's shfl latency stays hidden
                    h0 += fmaxf(c[0] - pv2, 0.0f);
                    h1 += fmaxf(c[1] - pv2, 0.0f);
                    h0 += fmaxf(c[2] - pv2, 0.0f);
                    h1 += fmaxf(c[3] - pv2, 0.0f);
                }
                h0 += fmaxf(c[0] - pv1, 0.0f);
                h1 += fmaxf(c[1] - pv1, 0.0f);
                h0 += fmaxf(c[2] - pv1, 0.0f);
                h1 += fmaxf(c[3] - pv1, 0.0f);
            }
        }
    }

    // One MUFU log per thread
    float bce = base + __logf(prod);
    float v = 0.7f * bce + 0.3f * (h0 + h1);

    // ---- Warp reduce ----
#pragma unroll
    for (int o = 16; o > 0; o >>= 1)
        v += __shfl_xor_sync(0xffffffffu, v, o);
    if (lane == 0) s_warp[wid] = v;
    __syncthreads();

    // ---- Block reduce (warp 0) + publish + ticket ----
    if (wid == 0) {
        float s = (lane < WARPS_PER_BLOCK) ? s_warp[lane] : 0.0f;
#pragma unroll
        for (int o = 16; o > 0; o >>= 1)
            s += __shfl_xor_sync(0xffffffffu, s, o);
        if (lane == 0) {
            g_partials[blockIdx.x] = s;
            __threadfence();
            int t = atomicAdd(&g_ticket, 1);
            s_is_last = (t == N_BLOCKS - 1);
        }
    }
    __syncthreads();

    // ---- Last block: deterministic reduction of 1024 partials ----
    if (s_is_last) {
        __threadfence();
        float s = 0.0f;
#pragma unroll
        for (int i = 0; i < N_BLOCKS / THREADS_PER_BLOCK; i++)   // 4 each
            s += g_partials[threadIdx.x + i * THREADS_PER_BLOCK];
#pragma unroll
        for (int o = 16; o > 0; o >>= 1)
            s += __shfl_xor_sync(0xffffffffu, s, o);
        if (lane == 0) s_warp[wid] = s;
        __syncthreads();
        if (wid == 0) {
            float r2 = (lane < WARPS_PER_BLOCK) ? s_warp[lane] : 0.0f;
#pragma unroll
            for (int o = 16; o > 0; o >>= 1)
                r2 += __shfl_xor_sync(0xffffffffu, r2, o);
            if (lane == 0) {
                out[0] = r2 * (1.0f / ((float)V_DIM * (float)N_ROWS));
                g_ticket = 0;   // reset for graph replay
            }
        }
    }
}

extern "C" void kernel_launch(void* const* d_in, const int* in_sizes, int n_in,
                              void* d_out, int out_size)
{
    const float* logits  = (const float*)d_in[0];
    const float* targets = (const float*)d_in[1];
    float* out = (float*)d_out;

    fused_loss_kernel<<<N_BLOCKS, THREADS_PER_BLOCK>>>(logits, targets, out);
}

// round 10
// speedup vs baseline: 1.0642x; 1.0183x over previous
#include <cuda_runtime.h>
#include <cuda_bf16.h>
#include <cstdint>

#define B_DIM 16
#define T_DIM 1024
#define V_DIM 128
#define N_ROWS (B_DIM * T_DIM)                  // 16384
#define WARPS_PER_BLOCK 8
#define THREADS_PER_BLOCK (WARPS_PER_BLOCK * 32)   // 256
#define ROWS_PER_WARP 2
#define ROWS_PER_BLOCK (WARPS_PER_BLOCK * ROWS_PER_WARP)   // 16
#define N_BLOCKS (N_ROWS / ROWS_PER_BLOCK)      // 1024
#define POS_SLOTS 132                            // 128 max + 4 pad; 528B = 16B-aligned

// Scratch (no device allocation allowed)
__device__ float g_partials[N_BLOCKS];
__device__ int   g_ticket = 0;

__global__ __launch_bounds__(THREADS_PER_BLOCK)
void fused_loss_kernel(const float* __restrict__ logits,
                       const float* __restrict__ targets,
                       float* __restrict__ out)
{
    __shared__ float s_pos[WARPS_PER_BLOCK][ROWS_PER_WARP][POS_SLOTS];
    __shared__ float s_warp[WARPS_PER_BLOCK];
    __shared__ bool  s_is_last;

    const int lane  = threadIdx.x & 31;
    const int wid   = threadIdx.x >> 5;
    const int row0  = (blockIdx.x * WARPS_PER_BLOCK + wid) * ROWS_PER_WARP;
    const unsigned lanemask_lt = (1u << lane) - 1u;

    // ---- Front-batched loads: 2 rows x (logits,targets), float4 per lane ----
    float4 xv0 = reinterpret_cast<const float4*>(logits  + (size_t)row0 * V_DIM)[lane];
    float4 tv0 = reinterpret_cast<const float4*>(targets + (size_t)row0 * V_DIM)[lane];
    float4 xv1 = reinterpret_cast<const float4*>(logits  + (size_t)(row0 + 1) * V_DIM)[lane];
    float4 tv1 = reinterpret_cast<const float4*>(targets + (size_t)(row0 + 1) * V_DIM)[lane];

    float base = 0.0f;            // sum of max(x,0) - x*t
    float h0 = 0.0f, h1 = 0.0f;   // hinge accumulators (ILP)
    float prod = 1.0f;            // product of (1 + e^-|x|): 8 factors <= 256

#pragma unroll
    for (int r = 0; r < ROWS_PER_WARP; r++) {
        float xs[4], ts[4];
        if (r == 0) { xs[0]=xv0.x; xs[1]=xv0.y; xs[2]=xv0.z; xs[3]=xv0.w;
                      ts[0]=tv0.x; ts[1]=tv0.y; ts[2]=tv0.z; ts[3]=tv0.w; }
        else        { xs[0]=xv1.x; xs[1]=xv1.y; xs[2]=xv1.z; xs[3]=xv1.w;
                      ts[0]=tv1.x; ts[1]=tv1.y; ts[2]=tv1.z; ts[3]=tv1.w; }

        // ---- BCE pieces ----
#pragma unroll
        for (int i = 0; i < 4; i++) {
            base += fmaxf(xs[i], 0.0f);
            base  = fmaf(-xs[i], ts[i], base);
            prod *= (1.0f + __expf(-fabsf(xs[i])));
        }

        // ---- Compact positives into smem (only sync ops in the kernel body) ----
        int cnt = 0;
#pragma unroll
        for (int i = 0; i < 4; i++) {
            bool pi = ts[i] > 0.5f;
            unsigned m = __ballot_sync(0xffffffffu, pi);
            if (pi) s_pos[wid][r][cnt + __popc(m & lanemask_lt)] = xs[i];
            cnt += __popc(m);
        }
        if (lane < 4) s_pos[wid][r][cnt + lane] = 1.0e30f;   // pad one group
        __syncwarp();

        // ---- c[i]: arithmetic self-exclusion (positives -> -1e30) ----
        float c[4];
#pragma unroll
        for (int i = 0; i < 4; i++)
            c[i] = fmaf(ts[i], -1.0e30f, 1.0f + xs[i]);

        // ---- Hinge: warp-uniform loop, 4 positives per LDS.128, no shfl ----
        int n4 = (cnt + 3) >> 2;                 // groups of 4 (pad covers tail)
        const float4* pg = reinterpret_cast<const float4*>(&s_pos[wid][r][0]);
        for (int k4 = 0; k4 < n4; k4++) {
            float4 P = pg[k4];                   // broadcast LDS.128
            float pk[4] = {P.x, P.y, P.z, P.w};
#pragma unroll
            for (int j = 0; j < 4; j++) {
                h0 += fmaxf(c[0] - pk[j], 0.0f);
                h1 += fmaxf(c[1] - pk[j], 0.0f);
                h0 += fmaxf(c[2] - pk[j], 0.0f);
                h1 += fmaxf(c[3] - pk[j], 0.0f);
            }
        }
    }

    // One MUFU log per thread
    float bce = base + __logf(prod);
    float v = 0.7f * bce + 0.3f * (h0 + h1);

    // ---- Warp reduce ----
#pragma unroll
    for (int o = 16; o > 0; o >>= 1)
        v += __shfl_xor_sync(0xffffffffu, v, o);
    if (lane == 0) s_warp[wid] = v;
    __syncthreads();

    // ---- Block reduce (warp 0) + publish + ticket ----
    if (wid == 0) {
        float s = (lane < WARPS_PER_BLOCK) ? s_warp[lane] : 0.0f;
#pragma unroll
        for (int o = 16; o > 0; o >>= 1)
            s += __shfl_xor_sync(0xffffffffu, s, o);
        if (lane == 0) {
            g_partials[blockIdx.x] = s;
            __threadfence();
            int t = atomicAdd(&g_ticket, 1);
            s_is_last = (t == N_BLOCKS - 1);
        }
    }
    __syncthreads();

    // ---- Last block: deterministic reduction of 1024 partials ----
    if (s_is_last) {
        __threadfence();
        float s = 0.0f;
#pragma unroll
        for (int i = 0; i < N_BLOCKS / THREADS_PER_BLOCK; i++)   // 4 each
            s += g_partials[threadIdx.x + i * THREADS_PER_BLOCK];
#pragma unroll
        for (int o = 16; o > 0; o >>= 1)
            s += __shfl_xor_sync(0xffffffffu, s, o);
        if (lane == 0) s_warp[wid] = s;
        __syncthreads();
        if (wid == 0) {
            float r2 = (lane < WARPS_PER_BLOCK) ? s_warp[lane] : 0.0f;
#pragma unroll
            for (int o = 16; o > 0; o >>= 1)
                r2 += __shfl_xor_sync(0xffffffffu, r2, o);
            if (lane == 0) {
                out[0] = r2 * (1.0f / ((float)V_DIM * (float)N_ROWS));
                g_ticket = 0;   // reset for graph replay
            }
        }
    }
}

extern "C" void kernel_launch(void* const* d_in, const int* in_sizes, int n_in,
                              void* d_out, int out_size)
{
    const float* logits  = (const float*)d_in[0];
    const float* targets = (const float*)d_in[1];
    float* out = (float*)d_out;

    fused_loss_kernel<<<N_BLOCKS, THREADS_PER_BLOCK>>>(logits, targets, out);
}